// round 13
// baseline (speedup 1.0000x reference)
#include <cuda_runtime.h>
#include <cuda_fp16.h>
#include <math_constants.h>
#include <cstdint>

#define B_ 8
#define S_ 1024
#define H_ 1024
#define NH_ 16
#define HD_ 64
#define M_ (B_ * S_)        // 8192
#define LN_EPS 1e-12f

// fp32 scratch
__device__ float g_x[M_ * H_];    // residual-added pre-LN

// fp16 scratch (u16 bits)
__device__ unsigned short g_Xhi[M_ * H_];
__device__ unsigned short g_Whi[4 * H_ * H_];   // Wq,Wk,Wv,Wo
__device__ unsigned short g_Qh[M_ * H_];        // [B*NH][S][HD]
__device__ unsigned short g_Kh[M_ * H_];
__device__ unsigned short g_Vh[M_ * H_];
__device__ unsigned short g_Chi[M_ * H_];       // ctx fp16 [B,S,H]

// ---------------------------------------------------------------------------
// helpers
// ---------------------------------------------------------------------------
__device__ __forceinline__ uint32_t smem_u32(const void* p) {
    uint32_t a;
    asm("{ .reg .u64 t; cvta.to.shared.u64 t, %1; cvt.u32.u64 %0, t; }" : "=r"(a) : "l"(p));
    return a;
}
__device__ __forceinline__ void ldm_x4(uint32_t& r0, uint32_t& r1, uint32_t& r2, uint32_t& r3,
                                       uint32_t addr) {
    asm volatile("ldmatrix.sync.aligned.m8n8.x4.shared.b16 {%0,%1,%2,%3}, [%4];"
                 : "=r"(r0), "=r"(r1), "=r"(r2), "=r"(r3) : "r"(addr));
}
__device__ __forceinline__ void ldm_x4_t(uint32_t& r0, uint32_t& r1, uint32_t& r2, uint32_t& r3,
                                         uint32_t addr) {
    asm volatile("ldmatrix.sync.aligned.m8n8.x4.trans.shared.b16 {%0,%1,%2,%3}, [%4];"
                 : "=r"(r0), "=r"(r1), "=r"(r2), "=r"(r3) : "r"(addr));
}
__device__ __forceinline__ void mma_f16(float* d, const uint32_t* a, const uint32_t* b) {
    asm volatile(
        "mma.sync.aligned.m16n8k16.row.col.f32.f16.f16.f32 "
        "{%0,%1,%2,%3}, {%4,%5,%6,%7}, {%8,%9}, {%0,%1,%2,%3};"
        : "+f"(d[0]), "+f"(d[1]), "+f"(d[2]), "+f"(d[3])
        : "r"(a[0]), "r"(a[1]), "r"(a[2]), "r"(a[3]), "r"(b[0]), "r"(b[1]));
}
__device__ __forceinline__ void cp16(uint32_t dst, const void* src) {
    asm volatile("cp.async.cg.shared.global [%0], [%1], 16;" :: "r"(dst), "l"(src));
}
__device__ __forceinline__ void cp_commit() { asm volatile("cp.async.commit_group;"); }

__device__ __forceinline__ uint32_t pack2_f16(float a, float b) {
    __half ha = __float2half(a), hb = __float2half(b);
    return (uint32_t)__half_as_ushort(ha) | ((uint32_t)__half_as_ushort(hb) << 16);
}

// ---------------------------------------------------------------------------
// fused split: X + 4 weight matrices -> fp16, one launch
// ---------------------------------------------------------------------------
#define NX4 (M_ * H_ / 4)    // 2097152 float4s of X
#define NW4 (H_ * H_ / 4)    // 262144 float4s per weight
#define NSPLIT4 (NX4 + 4 * NW4)

__global__ __launch_bounds__(256) void split_all_kernel(
    const float* __restrict__ X,
    const float* __restrict__ Wq, const float* __restrict__ Wk,
    const float* __restrict__ Wv, const float* __restrict__ Wo,
    unsigned short* __restrict__ xhi, unsigned short* __restrict__ whi)
{
    int i = blockIdx.x * 256 + threadIdx.x;
    if (i >= NSPLIT4) return;
    const float* src;
    unsigned short* dst;
    int idx;
    if (i < NX4) {
        src = X; dst = xhi; idx = i;
    } else {
        int j = i - NX4;
        int w = j >> 18;             // j / NW4
        idx = j & (NW4 - 1);
        src = (w == 0) ? Wq : (w == 1) ? Wk : (w == 2) ? Wv : Wo;
        dst = whi + ((size_t)w << 20);
    }
    float4 v = ((const float4*)src)[idx];
    ushort4 hh;
    hh.x = __half_as_ushort(__float2half(v.x));
    hh.y = __half_as_ushort(__float2half(v.y));
    hh.z = __half_as_ushort(__float2half(v.z));
    hh.w = __half_as_ushort(__float2half(v.w));
    ((ushort4*)dst)[idx] = hh;
}

// ---------------------------------------------------------------------------
// cp.async 2-stage fp16 GEMM: C[m][n] = sum_k A[m][k]*W[n][k]
// BM=64 BN=64 BK=64, 128 thr (4 warps 2x2), warp tile 32x32.
// Fine tiles to cut wave-quantization tail. 36 KB smem.
// ---------------------------------------------------------------------------
#define BK 64
#define NCH (H_ / BK)        // 16
#define STR 72               // smem row stride (halves), 64 cols + 8 pad
#define MAT_H (64 * STR)     // 4608 halves per matrix tile
#define STG_H (2 * MAT_H)
#define GEMM_SMEM (2 * STG_H * 2)   // 36864 B

__global__ __launch_bounds__(128, 4) void gemm_kernel(
    const unsigned short* __restrict__ Ahi,
    int wbase,
    const float* __restrict__ bias0, const float* __restrict__ bias1,
    const float* __restrict__ bias2, const float* __restrict__ residual)
{
    extern __shared__ unsigned short sm[];
    const uint32_t sbase = smem_u32(sm);

    const int tid = threadIdx.x;
    const int wid = tid >> 5;
    const int lane = tid & 31;
    const int warp_m = wid & 1;      // 2 -> 32 rows each
    const int warp_n = wid >> 1;     // 2 -> 32 cols each
    const int w  = wbase + blockIdx.z;
    const int n0 = blockIdx.x * 64;
    const int m0 = blockIdx.y * 64;

    const unsigned short* Bhi = g_Whi + ((size_t)w << 20);
    const float* bias = (w == 1) ? bias1 : (w == 2) ? bias2 : bias0;

    const unsigned short* gsrc[2] = {Ahi, Bhi};
    const int gbase[2] = {m0, n0};

    auto issue_stage = [&](int c) {
        const int st = c & 1;
        const int kc = c * BK;
        #pragma unroll
        for (int t = 0; t < 8; t++) {
            int v = tid + t * 128;          // 0..1023
            int mat = v >> 9;
            int rem = v & 511;
            int row = rem >> 3;             // 0..63
            int g = (rem & 7) * 8;
            const unsigned short* src = gsrc[mat] + (size_t)(gbase[mat] + row) * H_ + kc + g;
            uint32_t dst = sbase + (uint32_t)(st * STG_H + mat * MAT_H + row * STR + g) * 2;
            cp16(dst, src);
        }
        cp_commit();
    };

    float C[2][4][4];
    #pragma unroll
    for (int a = 0; a < 2; a++)
        #pragma unroll
        for (int b = 0; b < 4; b++)
            #pragma unroll
            for (int c = 0; c < 4; c++) C[a][b][c] = 0.f;

    issue_stage(0);

    for (int c = 0; c < NCH; c++) {
        if (c + 1 < NCH) {
            issue_stage(c + 1);
            asm volatile("cp.async.wait_group 1;" ::: "memory");
        } else {
            asm volatile("cp.async.wait_group 0;" ::: "memory");
        }
        __syncthreads();

        const uint32_t stage = sbase + (uint32_t)(c & 1) * (STG_H * 2);

        #pragma unroll
        for (int ks = 0; ks < 4; ks++) {
            const int k0 = ks * 16;
            uint32_t ah[2][4];
            #pragma unroll
            for (int mt = 0; mt < 2; mt++) {
                int row = warp_m * 32 + mt * 16 + (lane & 15);
                int col = k0 + (lane >> 4) * 8;
                uint32_t off = (uint32_t)(row * STR + col) * 2;
                ldm_x4(ah[mt][0], ah[mt][1], ah[mt][2], ah[mt][3], stage + off);
            }
            #pragma unroll
            for (int ntp = 0; ntp < 2; ntp++) {
                int brow = warp_n * 32 + ntp * 16 + (lane & 7) + (lane >> 4) * 8;
                int bcol = k0 + ((lane >> 3) & 1) * 8;
                uint32_t off = (uint32_t)(brow * STR + bcol) * 2;
                uint32_t bh[4];
                ldm_x4(bh[0], bh[1], bh[2], bh[3], stage + MAT_H * 2 + off);
                #pragma unroll
                for (int nt2 = 0; nt2 < 2; nt2++) {
                    const int nt = ntp * 2 + nt2;
                    #pragma unroll
                    for (int mt = 0; mt < 2; mt++) {
                        mma_f16(C[mt][nt], ah[mt], &bh[nt2 * 2]);
                    }
                }
            }
        }
        __syncthreads();
    }

    // epilogue
    unsigned short* oh = (w == 0) ? g_Qh : (w == 1) ? g_Kh : g_Vh;
    #pragma unroll
    for (int mt = 0; mt < 2; mt++) {
        #pragma unroll
        for (int nt = 0; nt < 4; nt++) {
            const float* d = C[mt][nt];
            int m = m0 + warp_m * 32 + mt * 16 + (lane >> 2);
            int n = n0 + warp_n * 32 + nt * 8 + (lane & 3) * 2;
            float b0 = bias[n], b1 = bias[n + 1];
            if (w < 3) {
                int h = n >> 6, dd = n & 63;
                #pragma unroll
                for (int rr = 0; rr < 2; rr++) {
                    int mm = m + rr * 8;
                    int bb = mm >> 10, ss = mm & 1023;
                    size_t o = ((size_t)(bb * NH_ + h) * S_ + ss) * HD_ + dd;
                    *(uint32_t*)&oh[o] = pack2_f16(d[rr * 2 + 0] + b0, d[rr * 2 + 1] + b1);
                }
            } else {
                #pragma unroll
                for (int rr = 0; rr < 2; rr++) {
                    int mm = m + rr * 8;
                    size_t idx = (size_t)mm * H_ + n;
                    float2 res = *(const float2*)&residual[idx];
                    float2 o = make_float2(d[rr * 2 + 0] + b0 + res.x,
                                           d[rr * 2 + 1] + b1 + res.y);
                    *(float2*)&g_x[idx] = o;
                }
            }
        }
    }
}

// ---------------------------------------------------------------------------
// Tensor-core flash attention, fp16 single pass, fp32 softmax.
// grid (S/128=8, B*NH=128), 256 thr (8 warps, 16 q-rows each).
// ---------------------------------------------------------------------------
#define ASTR 72   // smem row stride (u16)

__global__ __launch_bounds__(256) void attn_kernel(const float* __restrict__ mask)
{
    __shared__ unsigned short Kh[64 * ASTR];
    __shared__ unsigned short Vh[64 * ASTR];
    __shared__ float msk[S_];

    const int bh  = blockIdx.y;
    const int qt  = blockIdx.x;
    const int tid = threadIdx.x;
    const int wid = tid >> 5;
    const int lane = tid & 31;
    const int b   = bh >> 4;
    const int h   = bh & 15;
    const size_t base = (size_t)bh * S_ * HD_;

    const uint32_t sKh = smem_u32(Kh);
    const uint32_t sVh = smem_u32(Vh);

    ((float4*)msk)[tid] = ((const float4*)(mask + (size_t)b * S_))[tid];

    // stage Q (128 rows): rows 0-63 -> Kh, 64-127 -> Vh
    #pragma unroll
    for (int t = 0; t < 4; t++) {
        int idx = tid + t * 256;            // 0..1023
        int row = idx >> 3, g = (idx & 7) * 8;
        size_t go = base + (size_t)(qt * 128 + row) * HD_ + g;
        unsigned short* dh = (row < 64) ? Kh : Vh;
        int r = row & 63;
        *(uint4*)&dh[r * ASTR + g] = *(const uint4*)&g_Qh[go];
    }
    __syncthreads();

    uint32_t qh[4][4];
    {
        const uint32_t bh_ = (wid < 4) ? sKh : sVh;
        int rbase = (wid & 3) * 16 + (lane & 15);
        #pragma unroll
        for (int ks = 0; ks < 4; ks++) {
            int col = ks * 16 + (lane >> 4) * 8;
            uint32_t off = (uint32_t)(rbase * ASTR + col) * 2;
            ldm_x4(qh[ks][0], qh[ks][1], qh[ks][2], qh[ks][3], bh_ + off);
        }
    }
    __syncthreads();

    float Co[8][4];
    #pragma unroll
    for (int i = 0; i < 8; i++)
        #pragma unroll
        for (int j = 0; j < 4; j++) Co[i][j] = 0.f;
    float m0 = -CUDART_INF_F, m1 = -CUDART_INF_F, l0 = 0.f, l1 = 0.f;

    for (int kt = 0; kt < S_ / 64; kt++) {
        #pragma unroll
        for (int t = 0; t < 2; t++) {
            int v = tid + t * 256;          // 0..511
            int row = v >> 3, g = (v & 7) * 8;
            size_t go = base + (size_t)(kt * 64 + row) * HD_ + g;
            *(uint4*)&Kh[row * ASTR + g] = *(const uint4*)&g_Kh[go];
            *(uint4*)&Vh[row * ASTR + g] = *(const uint4*)&g_Vh[go];
        }
        __syncthreads();

        // S = Q K^T
        float Cs[8][4];
        #pragma unroll
        for (int i = 0; i < 8; i++)
            #pragma unroll
            for (int j = 0; j < 4; j++) Cs[i][j] = 0.f;

        #pragma unroll
        for (int ks = 0; ks < 4; ks++) {
            #pragma unroll
            for (int ntp = 0; ntp < 4; ntp++) {
                int brow = ntp * 16 + (lane & 7) + (lane >> 4) * 8;
                int bcol = ks * 16 + ((lane >> 3) & 1) * 8;
                uint32_t off = (uint32_t)(brow * ASTR + bcol) * 2;
                uint32_t kbh[4];
                ldm_x4(kbh[0], kbh[1], kbh[2], kbh[3], sKh + off);
                #pragma unroll
                for (int nt2 = 0; nt2 < 2; nt2++) {
                    mma_f16(Cs[ntp * 2 + nt2], qh[ks], &kbh[nt2 * 2]);
                }
            }
        }

        // scale + mask + online softmax
        float mn0 = m0, mn1 = m1;
        #pragma unroll
        for (int nt = 0; nt < 8; nt++) {
            int col = kt * 64 + nt * 8 + (lane & 3) * 2;
            float mka = msk[col], mkb = msk[col + 1];
            Cs[nt][0] = fmaf(Cs[nt][0], 0.125f, mka);
            Cs[nt][1] = fmaf(Cs[nt][1], 0.125f, mkb);
            Cs[nt][2] = fmaf(Cs[nt][2], 0.125f, mka);
            Cs[nt][3] = fmaf(Cs[nt][3], 0.125f, mkb);
            mn0 = fmaxf(mn0, fmaxf(Cs[nt][0], Cs[nt][1]));
            mn1 = fmaxf(mn1, fmaxf(Cs[nt][2], Cs[nt][3]));
        }
        mn0 = fmaxf(mn0, __shfl_xor_sync(0xffffffffu, mn0, 1));
        mn0 = fmaxf(mn0, __shfl_xor_sync(0xffffffffu, mn0, 2));
        mn1 = fmaxf(mn1, __shfl_xor_sync(0xffffffffu, mn1, 1));
        mn1 = fmaxf(mn1, __shfl_xor_sync(0xffffffffu, mn1, 2));

        float f0 = __expf(m0 - mn0), f1 = __expf(m1 - mn1);
        m0 = mn0; m1 = mn1;
        l0 *= f0; l1 *= f1;
        #pragma unroll
        for (int nt = 0; nt < 8; nt++) {
            Co[nt][0] *= f0; Co[nt][1] *= f0;
            Co[nt][2] *= f1; Co[nt][3] *= f1;
        }
        #pragma unroll
        for (int nt = 0; nt < 8; nt++) {
            Cs[nt][0] = __expf(Cs[nt][0] - m0);
            Cs[nt][1] = __expf(Cs[nt][1] - m0);
            Cs[nt][2] = __expf(Cs[nt][2] - m1);
            Cs[nt][3] = __expf(Cs[nt][3] - m1);
            l0 += Cs[nt][0] + Cs[nt][1];
            l1 += Cs[nt][2] + Cs[nt][3];
        }

        // O += P V
        #pragma unroll
        for (int kc = 0; kc < 4; kc++) {
            uint32_t phi[4];
            phi[0] = pack2_f16(Cs[2 * kc][0],     Cs[2 * kc][1]);
            phi[1] = pack2_f16(Cs[2 * kc][2],     Cs[2 * kc][3]);
            phi[2] = pack2_f16(Cs[2 * kc + 1][0], Cs[2 * kc + 1][1]);
            phi[3] = pack2_f16(Cs[2 * kc + 1][2], Cs[2 * kc + 1][3]);
            #pragma unroll
            for (int ntp = 0; ntp < 4; ntp++) {
                uint32_t off = (uint32_t)((kc * 16 + (lane & 15)) * ASTR +
                                          ntp * 16 + (lane >> 4) * 8) * 2;
                uint32_t vbh[4];
                ldm_x4_t(vbh[0], vbh[1], vbh[2], vbh[3], sVh + off);
                #pragma unroll
                for (int nt2 = 0; nt2 < 2; nt2++) {
                    mma_f16(Co[ntp * 2 + nt2], phi, &vbh[nt2 * 2]);
                }
            }
        }
        __syncthreads();
    }

    l0 += __shfl_xor_sync(0xffffffffu, l0, 1);
    l0 += __shfl_xor_sync(0xffffffffu, l0, 2);
    l1 += __shfl_xor_sync(0xffffffffu, l1, 1);
    l1 += __shfl_xor_sync(0xffffffffu, l1, 2);
    float inv0 = 1.f / l0, inv1 = 1.f / l1;

    const int s0 = qt * 128 + wid * 16 + (lane >> 2);
    #pragma unroll
    for (int nt = 0; nt < 8; nt++) {
        int col = h * HD_ + nt * 8 + (lane & 3) * 2;
        size_t o0 = (size_t)(b * S_ + s0) * H_ + col;
        size_t o1 = (size_t)(b * S_ + s0 + 8) * H_ + col;
        *(uint32_t*)&g_Chi[o0] = pack2_f16(Co[nt][0] * inv0, Co[nt][1] * inv0);
        *(uint32_t*)&g_Chi[o1] = pack2_f16(Co[nt][2] * inv1, Co[nt][3] * inv1);
    }
}

// ---------------------------------------------------------------------------
// LayerNorm
// ---------------------------------------------------------------------------
__global__ __launch_bounds__(256) void ln_kernel(
    const float* __restrict__ gamma, const float* __restrict__ beta,
    float* __restrict__ out)
{
    const int row = blockIdx.x;
    const int tid = threadIdx.x;
    const float* x = g_x + (size_t)row * H_;

    float4 v = *(const float4*)&x[tid * 4];
    float s  = v.x + v.y + v.z + v.w;
    float ss = v.x * v.x + v.y * v.y + v.z * v.z + v.w * v.w;

    #pragma unroll
    for (int o = 16; o > 0; o >>= 1) {
        s  += __shfl_xor_sync(0xffffffffu, s,  o);
        ss += __shfl_xor_sync(0xffffffffu, ss, o);
    }
    __shared__ float rs[8], rss[8];
    int wid = tid >> 5, lid = tid & 31;
    if (lid == 0) { rs[wid] = s; rss[wid] = ss; }
    __syncthreads();
    if (wid == 0) {
        float a = (lid < 8) ? rs[lid]  : 0.f;
        float c = (lid < 8) ? rss[lid] : 0.f;
        #pragma unroll
        for (int o = 4; o > 0; o >>= 1) {
            a += __shfl_xor_sync(0xffffffffu, a, o);
            c += __shfl_xor_sync(0xffffffffu, c, o);
        }
        if (lid == 0) { rs[0] = a; rss[0] = c; }
    }
    __syncthreads();

    float mean = rs[0] * (1.f / H_);
    float var  = rss[0] * (1.f / H_) - mean * mean;
    float rstd = rsqrtf(var + LN_EPS);

    float4 g = *(const float4*)&gamma[tid * 4];
    float4 bt = *(const float4*)&beta[tid * 4];
    float4 y;
    y.x = (v.x - mean) * rstd * g.x + bt.x;
    y.y = (v.y - mean) * rstd * g.y + bt.y;
    y.z = (v.z - mean) * rstd * g.z + bt.z;
    y.w = (v.w - mean) * rstd * g.w + bt.w;
    *(float4*)&out[(size_t)row * H_ + tid * 4] = y;
}

// ---------------------------------------------------------------------------
extern "C" void kernel_launch(void* const* d_in, const int* in_sizes, int n_in,
                              void* d_out, int out_size)
{
    const float* hidden = (const float*)d_in[0];
    const float* mask   = (const float*)d_in[1];
    const float* Wq     = (const float*)d_in[2];
    const float* bq     = (const float*)d_in[3];
    const float* Wk     = (const float*)d_in[4];
    const float* bk     = (const float*)d_in[5];
    const float* Wv     = (const float*)d_in[6];
    const float* bv     = (const float*)d_in[7];
    const float* Wo     = (const float*)d_in[8];
    const float* bo     = (const float*)d_in[9];
    const float* gamma  = (const float*)d_in[10];
    const float* beta   = (const float*)d_in[11];
    float* out          = (float*)d_out;

    static int attr_set = 0;
    if (!attr_set) {
        cudaFuncSetAttribute(gemm_kernel, cudaFuncAttributeMaxDynamicSharedMemorySize, GEMM_SMEM);
        attr_set = 1;
    }

    unsigned short *xhi, *whi, *chi;
    cudaGetSymbolAddress((void**)&xhi, g_Xhi);
    cudaGetSymbolAddress((void**)&whi, g_Whi);
    cudaGetSymbolAddress((void**)&chi, g_Chi);

    split_all_kernel<<<(NSPLIT4 + 255) / 256, 256>>>(hidden, Wq, Wk, Wv, Wo, xhi, whi);

    dim3 qkv_grid(H_ / 64, M_ / 64, 3);
    gemm_kernel<<<qkv_grid, 128, GEMM_SMEM>>>(xhi, 0, bq, bk, bv, nullptr);

    dim3 attn_grid(S_ / 128, B_ * NH_);
    attn_kernel<<<attn_grid, 256>>>(mask);

    dim3 out_grid(H_ / 64, M_ / 64, 1);
    gemm_kernel<<<out_grid, 128, GEMM_SMEM>>>(chi, 3, bo, nullptr, nullptr, hidden);

    ln_kernel<<<M_, 256>>>(gamma, beta, out);
}

// round 14
// speedup vs baseline: 1.0341x; 1.0341x over previous
#include <cuda_runtime.h>
#include <cuda_fp16.h>
#include <math_constants.h>
#include <cstdint>

#define B_ 8
#define S_ 1024
#define H_ 1024
#define NH_ 16
#define HD_ 64
#define M_ (B_ * S_)        // 8192
#define LN_EPS 1e-12f

// fp32 scratch
__device__ float g_x[M_ * H_];    // residual-added pre-LN

// fp16 scratch (u16 bits)
__device__ unsigned short g_Xhi[M_ * H_];
__device__ unsigned short g_Whi[4 * H_ * H_];   // Wq,Wk,Wv,Wo
__device__ unsigned short g_Qh[M_ * H_];        // [B*NH][S][HD]
__device__ unsigned short g_Kh[M_ * H_];
__device__ unsigned short g_Vh[M_ * H_];
__device__ unsigned short g_Chi[M_ * H_];       // ctx fp16 [B,S,H]

// ---------------------------------------------------------------------------
// helpers
// ---------------------------------------------------------------------------
__device__ __forceinline__ uint32_t smem_u32(const void* p) {
    uint32_t a;
    asm("{ .reg .u64 t; cvta.to.shared.u64 t, %1; cvt.u32.u64 %0, t; }" : "=r"(a) : "l"(p));
    return a;
}
__device__ __forceinline__ void ldm_x4(uint32_t& r0, uint32_t& r1, uint32_t& r2, uint32_t& r3,
                                       uint32_t addr) {
    asm volatile("ldmatrix.sync.aligned.m8n8.x4.shared.b16 {%0,%1,%2,%3}, [%4];"
                 : "=r"(r0), "=r"(r1), "=r"(r2), "=r"(r3) : "r"(addr));
}
__device__ __forceinline__ void ldm_x4_t(uint32_t& r0, uint32_t& r1, uint32_t& r2, uint32_t& r3,
                                         uint32_t addr) {
    asm volatile("ldmatrix.sync.aligned.m8n8.x4.trans.shared.b16 {%0,%1,%2,%3}, [%4];"
                 : "=r"(r0), "=r"(r1), "=r"(r2), "=r"(r3) : "r"(addr));
}
__device__ __forceinline__ void mma_f16(float* d, const uint32_t* a, const uint32_t* b) {
    asm volatile(
        "mma.sync.aligned.m16n8k16.row.col.f32.f16.f16.f32 "
        "{%0,%1,%2,%3}, {%4,%5,%6,%7}, {%8,%9}, {%0,%1,%2,%3};"
        : "+f"(d[0]), "+f"(d[1]), "+f"(d[2]), "+f"(d[3])
        : "r"(a[0]), "r"(a[1]), "r"(a[2]), "r"(a[3]), "r"(b[0]), "r"(b[1]));
}
__device__ __forceinline__ void cp16(uint32_t dst, const void* src) {
    asm volatile("cp.async.cg.shared.global [%0], [%1], 16;" :: "r"(dst), "l"(src));
}
__device__ __forceinline__ void cp_commit() { asm volatile("cp.async.commit_group;"); }

__device__ __forceinline__ uint32_t pack2_f16(float a, float b) {
    __half ha = __float2half(a), hb = __float2half(b);
    return (uint32_t)__half_as_ushort(ha) | ((uint32_t)__half_as_ushort(hb) << 16);
}

// ---------------------------------------------------------------------------
// fused split: X + 4 weight matrices -> fp16, one launch
// ---------------------------------------------------------------------------
#define NX4 (M_ * H_ / 4)    // 2097152 float4s of X
#define NW4 (H_ * H_ / 4)    // 262144 float4s per weight
#define NSPLIT4 (NX4 + 4 * NW4)

__global__ __launch_bounds__(256) void split_all_kernel(
    const float* __restrict__ X,
    const float* __restrict__ Wq, const float* __restrict__ Wk,
    const float* __restrict__ Wv, const float* __restrict__ Wo,
    unsigned short* __restrict__ xhi, unsigned short* __restrict__ whi)
{
    int i = blockIdx.x * 256 + threadIdx.x;
    if (i >= NSPLIT4) return;
    const float* src;
    unsigned short* dst;
    int idx;
    if (i < NX4) {
        src = X; dst = xhi; idx = i;
    } else {
        int j = i - NX4;
        int w = j >> 18;             // j / NW4
        idx = j & (NW4 - 1);
        src = (w == 0) ? Wq : (w == 1) ? Wk : (w == 2) ? Wv : Wo;
        dst = whi + ((size_t)w << 20);
    }
    float4 v = ((const float4*)src)[idx];
    ushort4 hh;
    hh.x = __half_as_ushort(__float2half(v.x));
    hh.y = __half_as_ushort(__float2half(v.y));
    hh.z = __half_as_ushort(__float2half(v.z));
    hh.w = __half_as_ushort(__float2half(v.w));
    ((ushort4*)dst)[idx] = hh;
}

// ---------------------------------------------------------------------------
// cp.async 2-stage fp16 GEMM: C[m][n] = sum_k A[m][k]*W[n][k]
// BM=128 BN=64 BK=64, 256 thr (8 warps 4x2), warp tile 32x32.
// Low-register config: 3 CTAs/SM (24 warps) to feed the HMMA pipe.
// ---------------------------------------------------------------------------
#define BK 64
#define NCH (H_ / BK)        // 16
#define STR 72               // smem row stride (halves), 64 cols + 8 pad
#define A_H (128 * STR)      // 9216 halves
#define B_H (64 * STR)       // 4608 halves
#define STG_H (A_H + B_H)    // 13824 halves
#define GEMM_SMEM (2 * STG_H * 2)   // 55296 B

__global__ __launch_bounds__(256, 3) void gemm_kernel(
    const unsigned short* __restrict__ Ahi,
    int wbase,
    const float* __restrict__ bias0, const float* __restrict__ bias1,
    const float* __restrict__ bias2, const float* __restrict__ residual)
{
    extern __shared__ unsigned short sm[];
    const uint32_t sbase = smem_u32(sm);

    const int tid = threadIdx.x;
    const int wid = tid >> 5;
    const int lane = tid & 31;
    const int warp_m = wid & 3;      // 4 warps x 32 rows
    const int warp_n = wid >> 2;     // 2 warps x 32 cols
    const int w  = wbase + blockIdx.z;
    const int n0 = blockIdx.x * 64;
    const int m0 = blockIdx.y * 128;

    const unsigned short* Bhi = g_Whi + ((size_t)w << 20);
    const float* bias = (w == 1) ? bias1 : (w == 2) ? bias2 : bias0;

    auto issue_stage = [&](int c) {
        const int st = c & 1;
        const int kc = c * BK;
        #pragma unroll
        for (int t = 0; t < 6; t++) {
            int v = tid + t * 256;          // 0..1535
            uint32_t dst;
            const unsigned short* src;
            if (v < 1024) {                 // A: 128 rows x 8 groups
                int row = v >> 3, g = (v & 7) * 8;
                src = Ahi + (size_t)(m0 + row) * H_ + kc + g;
                dst = sbase + (uint32_t)(st * STG_H + row * STR + g) * 2;
            } else {                        // B: 64 rows x 8 groups
                int rem = v - 1024;
                int row = rem >> 3, g = (rem & 7) * 8;
                src = Bhi + (size_t)(n0 + row) * H_ + kc + g;
                dst = sbase + (uint32_t)(st * STG_H + A_H + row * STR + g) * 2;
            }
            cp16(dst, src);
        }
        cp_commit();
    };

    float C[2][4][4];
    #pragma unroll
    for (int a = 0; a < 2; a++)
        #pragma unroll
        for (int b = 0; b < 4; b++)
            #pragma unroll
            for (int c = 0; c < 4; c++) C[a][b][c] = 0.f;

    issue_stage(0);

    for (int c = 0; c < NCH; c++) {
        if (c + 1 < NCH) {
            issue_stage(c + 1);
            asm volatile("cp.async.wait_group 1;" ::: "memory");
        } else {
            asm volatile("cp.async.wait_group 0;" ::: "memory");
        }
        __syncthreads();

        const uint32_t stage = sbase + (uint32_t)(c & 1) * (STG_H * 2);

        #pragma unroll
        for (int ks = 0; ks < 4; ks++) {
            const int k0 = ks * 16;
            uint32_t ah[2][4];
            #pragma unroll
            for (int mt = 0; mt < 2; mt++) {
                int row = warp_m * 32 + mt * 16 + (lane & 15);
                int col = k0 + (lane >> 4) * 8;
                uint32_t off = (uint32_t)(row * STR + col) * 2;
                ldm_x4(ah[mt][0], ah[mt][1], ah[mt][2], ah[mt][3], stage + off);
            }
            #pragma unroll
            for (int ntp = 0; ntp < 2; ntp++) {
                int brow = warp_n * 32 + ntp * 16 + (lane & 7) + (lane >> 4) * 8;
                int bcol = k0 + ((lane >> 3) & 1) * 8;
                uint32_t off = (uint32_t)(brow * STR + bcol) * 2;
                uint32_t bh[4];
                ldm_x4(bh[0], bh[1], bh[2], bh[3], stage + A_H * 2 + off);
                #pragma unroll
                for (int nt2 = 0; nt2 < 2; nt2++) {
                    const int nt = ntp * 2 + nt2;
                    #pragma unroll
                    for (int mt = 0; mt < 2; mt++) {
                        mma_f16(C[mt][nt], ah[mt], &bh[nt2 * 2]);
                    }
                }
            }
        }
        __syncthreads();
    }

    // epilogue
    unsigned short* oh = (w == 0) ? g_Qh : (w == 1) ? g_Kh : g_Vh;
    #pragma unroll
    for (int mt = 0; mt < 2; mt++) {
        #pragma unroll
        for (int nt = 0; nt < 4; nt++) {
            const float* d = C[mt][nt];
            int m = m0 + warp_m * 32 + mt * 16 + (lane >> 2);
            int n = n0 + warp_n * 32 + nt * 8 + (lane & 3) * 2;
            float b0 = bias[n], b1 = bias[n + 1];
            if (w < 3) {
                int h = n >> 6, dd = n & 63;
                #pragma unroll
                for (int rr = 0; rr < 2; rr++) {
                    int mm = m + rr * 8;
                    int bb = mm >> 10, ss = mm & 1023;
                    size_t o = ((size_t)(bb * NH_ + h) * S_ + ss) * HD_ + dd;
                    *(uint32_t*)&oh[o] = pack2_f16(d[rr * 2 + 0] + b0, d[rr * 2 + 1] + b1);
                }
            } else {
                #pragma unroll
                for (int rr = 0; rr < 2; rr++) {
                    int mm = m + rr * 8;
                    size_t idx = (size_t)mm * H_ + n;
                    float2 res = *(const float2*)&residual[idx];
                    float2 o = make_float2(d[rr * 2 + 0] + b0 + res.x,
                                           d[rr * 2 + 1] + b1 + res.y);
                    *(float2*)&g_x[idx] = o;
                }
            }
        }
    }
}

// ---------------------------------------------------------------------------
// Tensor-core flash attention, fp16 single pass, fp32 softmax.
// grid (S/128=8, B*NH=128), 256 thr (8 warps, 16 q-rows each).
// ---------------------------------------------------------------------------
#define ASTR 72   // smem row stride (u16)

__global__ __launch_bounds__(256) void attn_kernel(const float* __restrict__ mask)
{
    __shared__ unsigned short Kh[64 * ASTR];
    __shared__ unsigned short Vh[64 * ASTR];
    __shared__ float msk[S_];

    const int bh  = blockIdx.y;
    const int qt  = blockIdx.x;
    const int tid = threadIdx.x;
    const int wid = tid >> 5;
    const int lane = tid & 31;
    const int b   = bh >> 4;
    const int h   = bh & 15;
    const size_t base = (size_t)bh * S_ * HD_;

    const uint32_t sKh = smem_u32(Kh);
    const uint32_t sVh = smem_u32(Vh);

    ((float4*)msk)[tid] = ((const float4*)(mask + (size_t)b * S_))[tid];

    // stage Q (128 rows): rows 0-63 -> Kh, 64-127 -> Vh
    #pragma unroll
    for (int t = 0; t < 4; t++) {
        int idx = tid + t * 256;            // 0..1023
        int row = idx >> 3, g = (idx & 7) * 8;
        size_t go = base + (size_t)(qt * 128 + row) * HD_ + g;
        unsigned short* dh = (row < 64) ? Kh : Vh;
        int r = row & 63;
        *(uint4*)&dh[r * ASTR + g] = *(const uint4*)&g_Qh[go];
    }
    __syncthreads();

    uint32_t qh[4][4];
    {
        const uint32_t bh_ = (wid < 4) ? sKh : sVh;
        int rbase = (wid & 3) * 16 + (lane & 15);
        #pragma unroll
        for (int ks = 0; ks < 4; ks++) {
            int col = ks * 16 + (lane >> 4) * 8;
            uint32_t off = (uint32_t)(rbase * ASTR + col) * 2;
            ldm_x4(qh[ks][0], qh[ks][1], qh[ks][2], qh[ks][3], bh_ + off);
        }
    }
    __syncthreads();

    float Co[8][4];
    #pragma unroll
    for (int i = 0; i < 8; i++)
        #pragma unroll
        for (int j = 0; j < 4; j++) Co[i][j] = 0.f;
    float m0 = -CUDART_INF_F, m1 = -CUDART_INF_F, l0 = 0.f, l1 = 0.f;

    for (int kt = 0; kt < S_ / 64; kt++) {
        #pragma unroll
        for (int t = 0; t < 2; t++) {
            int v = tid + t * 256;          // 0..511
            int row = v >> 3, g = (v & 7) * 8;
            size_t go = base + (size_t)(kt * 64 + row) * HD_ + g;
            *(uint4*)&Kh[row * ASTR + g] = *(const uint4*)&g_Kh[go];
            *(uint4*)&Vh[row * ASTR + g] = *(const uint4*)&g_Vh[go];
        }
        __syncthreads();

        // S = Q K^T
        float Cs[8][4];
        #pragma unroll
        for (int i = 0; i < 8; i++)
            #pragma unroll
            for (int j = 0; j < 4; j++) Cs[i][j] = 0.f;

        #pragma unroll
        for (int ks = 0; ks < 4; ks++) {
            #pragma unroll
            for (int ntp = 0; ntp < 4; ntp++) {
                int brow = ntp * 16 + (lane & 7) + (lane >> 4) * 8;
                int bcol = ks * 16 + ((lane >> 3) & 1) * 8;
                uint32_t off = (uint32_t)(brow * ASTR + bcol) * 2;
                uint32_t kbh[4];
                ldm_x4(kbh[0], kbh[1], kbh[2], kbh[3], sKh + off);
                #pragma unroll
                for (int nt2 = 0; nt2 < 2; nt2++) {
                    mma_f16(Cs[ntp * 2 + nt2], qh[ks], &kbh[nt2 * 2]);
                }
            }
        }

        // scale + mask + online softmax
        float mn0 = m0, mn1 = m1;
        #pragma unroll
        for (int nt = 0; nt < 8; nt++) {
            int col = kt * 64 + nt * 8 + (lane & 3) * 2;
            float mka = msk[col], mkb = msk[col + 1];
            Cs[nt][0] = fmaf(Cs[nt][0], 0.125f, mka);
            Cs[nt][1] = fmaf(Cs[nt][1], 0.125f, mkb);
            Cs[nt][2] = fmaf(Cs[nt][2], 0.125f, mka);
            Cs[nt][3] = fmaf(Cs[nt][3], 0.125f, mkb);
            mn0 = fmaxf(mn0, fmaxf(Cs[nt][0], Cs[nt][1]));
            mn1 = fmaxf(mn1, fmaxf(Cs[nt][2], Cs[nt][3]));
        }
        mn0 = fmaxf(mn0, __shfl_xor_sync(0xffffffffu, mn0, 1));
        mn0 = fmaxf(mn0, __shfl_xor_sync(0xffffffffu, mn0, 2));
        mn1 = fmaxf(mn1, __shfl_xor_sync(0xffffffffu, mn1, 1));
        mn1 = fmaxf(mn1, __shfl_xor_sync(0xffffffffu, mn1, 2));

        float f0 = __expf(m0 - mn0), f1 = __expf(m1 - mn1);
        m0 = mn0; m1 = mn1;
        l0 *= f0; l1 *= f1;
        #pragma unroll
        for (int nt = 0; nt < 8; nt++) {
            Co[nt][0] *= f0; Co[nt][1] *= f0;
            Co[nt][2] *= f1; Co[nt][3] *= f1;
        }
        #pragma unroll
        for (int nt = 0; nt < 8; nt++) {
            Cs[nt][0] = __expf(Cs[nt][0] - m0);
            Cs[nt][1] = __expf(Cs[nt][1] - m0);
            Cs[nt][2] = __expf(Cs[nt][2] - m1);
            Cs[nt][3] = __expf(Cs[nt][3] - m1);
            l0 += Cs[nt][0] + Cs[nt][1];
            l1 += Cs[nt][2] + Cs[nt][3];
        }

        // O += P V
        #pragma unroll
        for (int kc = 0; kc < 4; kc++) {
            uint32_t phi[4];
            phi[0] = pack2_f16(Cs[2 * kc][0],     Cs[2 * kc][1]);
            phi[1] = pack2_f16(Cs[2 * kc][2],     Cs[2 * kc][3]);
            phi[2] = pack2_f16(Cs[2 * kc + 1][0], Cs[2 * kc + 1][1]);
            phi[3] = pack2_f16(Cs[2 * kc + 1][2], Cs[2 * kc + 1][3]);
            #pragma unroll
            for (int ntp = 0; ntp < 4; ntp++) {
                uint32_t off = (uint32_t)((kc * 16 + (lane & 15)) * ASTR +
                                          ntp * 16 + (lane >> 4) * 8) * 2;
                uint32_t vbh[4];
                ldm_x4_t(vbh[0], vbh[1], vbh[2], vbh[3], sVh + off);
                #pragma unroll
                for (int nt2 = 0; nt2 < 2; nt2++) {
                    mma_f16(Co[ntp * 2 + nt2], phi, &vbh[nt2 * 2]);
                }
            }
        }
        __syncthreads();
    }

    l0 += __shfl_xor_sync(0xffffffffu, l0, 1);
    l0 += __shfl_xor_sync(0xffffffffu, l0, 2);
    l1 += __shfl_xor_sync(0xffffffffu, l1, 1);
    l1 += __shfl_xor_sync(0xffffffffu, l1, 2);
    float inv0 = 1.f / l0, inv1 = 1.f / l1;

    const int s0 = qt * 128 + wid * 16 + (lane >> 2);
    #pragma unroll
    for (int nt = 0; nt < 8; nt++) {
        int col = h * HD_ + nt * 8 + (lane & 3) * 2;
        size_t o0 = (size_t)(b * S_ + s0) * H_ + col;
        size_t o1 = (size_t)(b * S_ + s0 + 8) * H_ + col;
        *(uint32_t*)&g_Chi[o0] = pack2_f16(Co[nt][0] * inv0, Co[nt][1] * inv0);
        *(uint32_t*)&g_Chi[o1] = pack2_f16(Co[nt][2] * inv1, Co[nt][3] * inv1);
    }
}

// ---------------------------------------------------------------------------
// LayerNorm
// ---------------------------------------------------------------------------
__global__ __launch_bounds__(256) void ln_kernel(
    const float* __restrict__ gamma, const float* __restrict__ beta,
    float* __restrict__ out)
{
    const int row = blockIdx.x;
    const int tid = threadIdx.x;
    const float* x = g_x + (size_t)row * H_;

    float4 v = *(const float4*)&x[tid * 4];
    float s  = v.x + v.y + v.z + v.w;
    float ss = v.x * v.x + v.y * v.y + v.z * v.z + v.w * v.w;

    #pragma unroll
    for (int o = 16; o > 0; o >>= 1) {
        s  += __shfl_xor_sync(0xffffffffu, s,  o);
        ss += __shfl_xor_sync(0xffffffffu, ss, o);
    }
    __shared__ float rs[8], rss[8];
    int wid = tid >> 5, lid = tid & 31;
    if (lid == 0) { rs[wid] = s; rss[wid] = ss; }
    __syncthreads();
    if (wid == 0) {
        float a = (lid < 8) ? rs[lid]  : 0.f;
        float c = (lid < 8) ? rss[lid] : 0.f;
        #pragma unroll
        for (int o = 4; o > 0; o >>= 1) {
            a += __shfl_xor_sync(0xffffffffu, a, o);
            c += __shfl_xor_sync(0xffffffffu, c, o);
        }
        if (lid == 0) { rs[0] = a; rss[0] = c; }
    }
    __syncthreads();

    float mean = rs[0] * (1.f / H_);
    float var  = rss[0] * (1.f / H_) - mean * mean;
    float rstd = rsqrtf(var + LN_EPS);

    float4 g = *(const float4*)&gamma[tid * 4];
    float4 bt = *(const float4*)&beta[tid * 4];
    float4 y;
    y.x = (v.x - mean) * rstd * g.x + bt.x;
    y.y = (v.y - mean) * rstd * g.y + bt.y;
    y.z = (v.z - mean) * rstd * g.z + bt.z;
    y.w = (v.w - mean) * rstd * g.w + bt.w;
    *(float4*)&out[(size_t)row * H_ + tid * 4] = y;
}

// ---------------------------------------------------------------------------
extern "C" void kernel_launch(void* const* d_in, const int* in_sizes, int n_in,
                              void* d_out, int out_size)
{
    const float* hidden = (const float*)d_in[0];
    const float* mask   = (const float*)d_in[1];
    const float* Wq     = (const float*)d_in[2];
    const float* bq     = (const float*)d_in[3];
    const float* Wk     = (const float*)d_in[4];
    const float* bk     = (const float*)d_in[5];
    const float* Wv     = (const float*)d_in[6];
    const float* bv     = (const float*)d_in[7];
    const float* Wo     = (const float*)d_in[8];
    const float* bo     = (const float*)d_in[9];
    const float* gamma  = (const float*)d_in[10];
    const float* beta   = (const float*)d_in[11];
    float* out          = (float*)d_out;

    static int attr_set = 0;
    if (!attr_set) {
        cudaFuncSetAttribute(gemm_kernel, cudaFuncAttributeMaxDynamicSharedMemorySize, GEMM_SMEM);
        attr_set = 1;
    }

    unsigned short *xhi, *whi, *chi;
    cudaGetSymbolAddress((void**)&xhi, g_Xhi);
    cudaGetSymbolAddress((void**)&whi, g_Whi);
    cudaGetSymbolAddress((void**)&chi, g_Chi);

    split_all_kernel<<<(NSPLIT4 + 255) / 256, 256>>>(hidden, Wq, Wk, Wv, Wo, xhi, whi);

    dim3 qkv_grid(H_ / 64, M_ / 128, 3);
    gemm_kernel<<<qkv_grid, 256, GEMM_SMEM>>>(xhi, 0, bq, bk, bv, nullptr);

    dim3 attn_grid(S_ / 128, B_ * NH_);
    attn_kernel<<<attn_grid, 256>>>(mask);

    dim3 out_grid(H_ / 64, M_ / 128, 1);
    gemm_kernel<<<out_grid, 256, GEMM_SMEM>>>(chi, 3, bo, nullptr, nullptr, hidden);

    ln_kernel<<<M_, 256>>>(gamma, beta, out);
}

// round 15
// speedup vs baseline: 1.2226x; 1.1822x over previous
#include <cuda_runtime.h>
#include <cuda_fp16.h>
#include <math_constants.h>
#include <cstdint>

#define B_ 8
#define S_ 1024
#define H_ 1024
#define NH_ 16
#define HD_ 64
#define M_ (B_ * S_)        // 8192
#define LN_EPS 1e-12f

// fp32 scratch
__device__ float g_x[M_ * H_];    // residual-added pre-LN

// fp16 scratch (u16 bits)
__device__ unsigned short g_Xhi[M_ * H_];
__device__ unsigned short g_Whi[4 * H_ * H_];   // Wq,Wk,Wv,Wo
__device__ unsigned short g_Qh[M_ * H_];        // [B*NH][S][HD]
__device__ unsigned short g_Kh[M_ * H_];
__device__ unsigned short g_Vh[M_ * H_];
__device__ unsigned short g_Chi[M_ * H_];       // ctx fp16 [B,S,H]

// ---------------------------------------------------------------------------
// helpers
// ---------------------------------------------------------------------------
__device__ __forceinline__ uint32_t smem_u32(const void* p) {
    uint32_t a;
    asm("{ .reg .u64 t; cvta.to.shared.u64 t, %1; cvt.u32.u64 %0, t; }" : "=r"(a) : "l"(p));
    return a;
}
__device__ __forceinline__ void ldm_x4(uint32_t& r0, uint32_t& r1, uint32_t& r2, uint32_t& r3,
                                       uint32_t addr) {
    asm volatile("ldmatrix.sync.aligned.m8n8.x4.shared.b16 {%0,%1,%2,%3}, [%4];"
                 : "=r"(r0), "=r"(r1), "=r"(r2), "=r"(r3) : "r"(addr));
}
__device__ __forceinline__ void ldm_x4_t(uint32_t& r0, uint32_t& r1, uint32_t& r2, uint32_t& r3,
                                         uint32_t addr) {
    asm volatile("ldmatrix.sync.aligned.m8n8.x4.trans.shared.b16 {%0,%1,%2,%3}, [%4];"
                 : "=r"(r0), "=r"(r1), "=r"(r2), "=r"(r3) : "r"(addr));
}
__device__ __forceinline__ void mma_f16(float* d, const uint32_t* a, const uint32_t* b) {
    asm volatile(
        "mma.sync.aligned.m16n8k16.row.col.f32.f16.f16.f32 "
        "{%0,%1,%2,%3}, {%4,%5,%6,%7}, {%8,%9}, {%0,%1,%2,%3};"
        : "+f"(d[0]), "+f"(d[1]), "+f"(d[2]), "+f"(d[3])
        : "r"(a[0]), "r"(a[1]), "r"(a[2]), "r"(a[3]), "r"(b[0]), "r"(b[1]));
}
__device__ __forceinline__ void cp16(uint32_t dst, const void* src) {
    asm volatile("cp.async.cg.shared.global [%0], [%1], 16;" :: "r"(dst), "l"(src));
}
__device__ __forceinline__ void cp_commit() { asm volatile("cp.async.commit_group;"); }

__device__ __forceinline__ uint32_t pack2_f16(float a, float b) {
    __half ha = __float2half(a), hb = __float2half(b);
    return (uint32_t)__half_as_ushort(ha) | ((uint32_t)__half_as_ushort(hb) << 16);
}

// ---------------------------------------------------------------------------
// fused split: X + 4 weight matrices -> fp16, one launch
// ---------------------------------------------------------------------------
#define NX4 (M_ * H_ / 4)    // 2097152 float4s of X
#define NW4 (H_ * H_ / 4)    // 262144 float4s per weight
#define NSPLIT4 (NX4 + 4 * NW4)

__global__ __launch_bounds__(256) void split_all_kernel(
    const float* __restrict__ X,
    const float* __restrict__ Wq, const float* __restrict__ Wk,
    const float* __restrict__ Wv, const float* __restrict__ Wo,
    unsigned short* __restrict__ xhi, unsigned short* __restrict__ whi)
{
    int i = blockIdx.x * 256 + threadIdx.x;
    if (i >= NSPLIT4) return;
    const float* src;
    unsigned short* dst;
    int idx;
    if (i < NX4) {
        src = X; dst = xhi; idx = i;
    } else {
        int j = i - NX4;
        int w = j >> 18;             // j / NW4
        idx = j & (NW4 - 1);
        src = (w == 0) ? Wq : (w == 1) ? Wk : (w == 2) ? Wv : Wo;
        dst = whi + ((size_t)w << 20);
    }
    float4 v = ((const float4*)src)[idx];
    ushort4 hh;
    hh.x = __half_as_ushort(__float2half(v.x));
    hh.y = __half_as_ushort(__float2half(v.y));
    hh.z = __half_as_ushort(__float2half(v.z));
    hh.w = __half_as_ushort(__float2half(v.w));
    ((ushort4*)dst)[idx] = hh;
}

// ---------------------------------------------------------------------------
// cp.async 2-stage fp16 GEMM: C[m][n] = sum_k A[m][k]*W[n][k]
// BM=128 BN=64 BK=64, 256 thr (8 warps 4x2), warp tile 32x32, 3 CTAs/SM.
// ---------------------------------------------------------------------------
#define BK 64
#define NCH (H_ / BK)        // 16
#define STR 72               // smem row stride (halves), 64 cols + 8 pad
#define A_H (128 * STR)      // 9216 halves
#define B_H (64 * STR)       // 4608 halves
#define STG_H (A_H + B_H)    // 13824 halves
#define GEMM_SMEM (2 * STG_H * 2)   // 55296 B

__global__ __launch_bounds__(256, 3) void gemm_kernel(
    const unsigned short* __restrict__ Ahi,
    int wbase,
    const float* __restrict__ bias0, const float* __restrict__ bias1,
    const float* __restrict__ bias2, const float* __restrict__ residual)
{
    extern __shared__ unsigned short sm[];
    const uint32_t sbase = smem_u32(sm);

    const int tid = threadIdx.x;
    const int wid = tid >> 5;
    const int lane = tid & 31;
    const int warp_m = wid & 3;
    const int warp_n = wid >> 2;
    const int w  = wbase + blockIdx.z;
    const int n0 = blockIdx.x * 64;
    const int m0 = blockIdx.y * 128;

    const unsigned short* Bhi = g_Whi + ((size_t)w << 20);
    const float* bias = (w == 1) ? bias1 : (w == 2) ? bias2 : bias0;

    auto issue_stage = [&](int c) {
        const int st = c & 1;
        const int kc = c * BK;
        #pragma unroll
        for (int t = 0; t < 6; t++) {
            int v = tid + t * 256;          // 0..1535
            uint32_t dst;
            const unsigned short* src;
            if (v < 1024) {                 // A: 128 rows x 8 groups
                int row = v >> 3, g = (v & 7) * 8;
                src = Ahi + (size_t)(m0 + row) * H_ + kc + g;
                dst = sbase + (uint32_t)(st * STG_H + row * STR + g) * 2;
            } else {                        // B: 64 rows x 8 groups
                int rem = v - 1024;
                int row = rem >> 3, g = (rem & 7) * 8;
                src = Bhi + (size_t)(n0 + row) * H_ + kc + g;
                dst = sbase + (uint32_t)(st * STG_H + A_H + row * STR + g) * 2;
            }
            cp16(dst, src);
        }
        cp_commit();
    };

    float C[2][4][4];
    #pragma unroll
    for (int a = 0; a < 2; a++)
        #pragma unroll
        for (int b = 0; b < 4; b++)
            #pragma unroll
            for (int c = 0; c < 4; c++) C[a][b][c] = 0.f;

    issue_stage(0);

    for (int c = 0; c < NCH; c++) {
        if (c + 1 < NCH) {
            issue_stage(c + 1);
            asm volatile("cp.async.wait_group 1;" ::: "memory");
        } else {
            asm volatile("cp.async.wait_group 0;" ::: "memory");
        }
        __syncthreads();

        const uint32_t stage = sbase + (uint32_t)(c & 1) * (STG_H * 2);

        #pragma unroll
        for (int ks = 0; ks < 4; ks++) {
            const int k0 = ks * 16;
            uint32_t ah[2][4];
            #pragma unroll
            for (int mt = 0; mt < 2; mt++) {
                int row = warp_m * 32 + mt * 16 + (lane & 15);
                int col = k0 + (lane >> 4) * 8;
                uint32_t off = (uint32_t)(row * STR + col) * 2;
                ldm_x4(ah[mt][0], ah[mt][1], ah[mt][2], ah[mt][3], stage + off);
            }
            #pragma unroll
            for (int ntp = 0; ntp < 2; ntp++) {
                int brow = warp_n * 32 + ntp * 16 + (lane & 7) + (lane >> 4) * 8;
                int bcol = k0 + ((lane >> 3) & 1) * 8;
                uint32_t off = (uint32_t)(brow * STR + bcol) * 2;
                uint32_t bh[4];
                ldm_x4(bh[0], bh[1], bh[2], bh[3], stage + A_H * 2 + off);
                #pragma unroll
                for (int nt2 = 0; nt2 < 2; nt2++) {
                    const int nt = ntp * 2 + nt2;
                    #pragma unroll
                    for (int mt = 0; mt < 2; mt++) {
                        mma_f16(C[mt][nt], ah[mt], &bh[nt2 * 2]);
                    }
                }
            }
        }
        __syncthreads();
    }

    // epilogue
    unsigned short* oh = (w == 0) ? g_Qh : (w == 1) ? g_Kh : g_Vh;
    #pragma unroll
    for (int mt = 0; mt < 2; mt++) {
        #pragma unroll
        for (int nt = 0; nt < 4; nt++) {
            const float* d = C[mt][nt];
            int m = m0 + warp_m * 32 + mt * 16 + (lane >> 2);
            int n = n0 + warp_n * 32 + nt * 8 + (lane & 3) * 2;
            float b0 = bias[n], b1 = bias[n + 1];
            if (w < 3) {
                int h = n >> 6, dd = n & 63;
                #pragma unroll
                for (int rr = 0; rr < 2; rr++) {
                    int mm = m + rr * 8;
                    int bb = mm >> 10, ss = mm & 1023;
                    size_t o = ((size_t)(bb * NH_ + h) * S_ + ss) * HD_ + dd;
                    *(uint32_t*)&oh[o] = pack2_f16(d[rr * 2 + 0] + b0, d[rr * 2 + 1] + b1);
                }
            } else {
                #pragma unroll
                for (int rr = 0; rr < 2; rr++) {
                    int mm = m + rr * 8;
                    size_t idx = (size_t)mm * H_ + n;
                    float2 res = *(const float2*)&residual[idx];
                    float2 o = make_float2(d[rr * 2 + 0] + b0 + res.x,
                                           d[rr * 2 + 1] + b1 + res.y);
                    *(float2*)&g_x[idx] = o;
                }
            }
        }
    }
}

// ---------------------------------------------------------------------------
// Tensor-core flash attention, fp16 single pass, fp32 softmax.
// cp.async double-buffered K/V tiles.
// grid (S/128=8, B*NH=128), 256 thr (8 warps, 16 q-rows each).
// ---------------------------------------------------------------------------
#define ASTR 72   // smem row stride (u16)
#define KVB (64 * ASTR)   // halves per K (or V) buffer

__global__ __launch_bounds__(256) void attn_kernel(const float* __restrict__ mask)
{
    __shared__ unsigned short Kh[2][KVB];
    __shared__ unsigned short Vh[2][KVB];
    __shared__ float msk[S_];

    const int bh  = blockIdx.y;
    const int qt  = blockIdx.x;
    const int tid = threadIdx.x;
    const int wid = tid >> 5;
    const int lane = tid & 31;
    const int b   = bh >> 4;
    const int h   = bh & 15;
    const size_t base = (size_t)bh * S_ * HD_;

    const uint32_t sKh = smem_u32(Kh);
    const uint32_t sVh = smem_u32(Vh);

    ((float4*)msk)[tid] = ((const float4*)(mask + (size_t)b * S_))[tid];

    // stage Q (128 rows) into buffer 0: rows 0-63 -> Kh[0], 64-127 -> Vh[0]
    #pragma unroll
    for (int t = 0; t < 4; t++) {
        int idx = tid + t * 256;            // 0..1023
        int row = idx >> 3, g = (idx & 7) * 8;
        size_t go = base + (size_t)(qt * 128 + row) * HD_ + g;
        unsigned short* dh = (row < 64) ? Kh[0] : Vh[0];
        int r = row & 63;
        *(uint4*)&dh[r * ASTR + g] = *(const uint4*)&g_Qh[go];
    }
    __syncthreads();

    uint32_t qh[4][4];
    {
        const uint32_t bh_ = (wid < 4) ? sKh : sVh;
        int rbase = (wid & 3) * 16 + (lane & 15);
        #pragma unroll
        for (int ks = 0; ks < 4; ks++) {
            int col = ks * 16 + (lane >> 4) * 8;
            uint32_t off = (uint32_t)(rbase * ASTR + col) * 2;
            ldm_x4(qh[ks][0], qh[ks][1], qh[ks][2], qh[ks][3], bh_ + off);
        }
    }
    __syncthreads();

    // cp.async loader for K/V tile kt into buffer kt&1
    auto issue_kv = [&](int kt) {
        const uint32_t boff = (uint32_t)((kt & 1) * KVB) * 2;
        #pragma unroll
        for (int t = 0; t < 2; t++) {
            int v = tid + t * 256;          // 0..511
            int row = v >> 3, g = (v & 7) * 8;
            size_t go = base + (size_t)(kt * 64 + row) * HD_ + g;
            uint32_t so = (uint32_t)(row * ASTR + g) * 2;
            cp16(sKh + boff + so, &g_Kh[go]);
            cp16(sVh + boff + so, &g_Vh[go]);
        }
        cp_commit();
    };

    float Co[8][4];
    #pragma unroll
    for (int i = 0; i < 8; i++)
        #pragma unroll
        for (int j = 0; j < 4; j++) Co[i][j] = 0.f;
    float m0 = -CUDART_INF_F, m1 = -CUDART_INF_F, l0 = 0.f, l1 = 0.f;

    issue_kv(0);

    for (int kt = 0; kt < S_ / 64; kt++) {
        if (kt + 1 < S_ / 64) {
            issue_kv(kt + 1);
            asm volatile("cp.async.wait_group 1;" ::: "memory");
        } else {
            asm volatile("cp.async.wait_group 0;" ::: "memory");
        }
        __syncthreads();

        const uint32_t boff = (uint32_t)((kt & 1) * KVB) * 2;

        // S = Q K^T
        float Cs[8][4];
        #pragma unroll
        for (int i = 0; i < 8; i++)
            #pragma unroll
            for (int j = 0; j < 4; j++) Cs[i][j] = 0.f;

        #pragma unroll
        for (int ks = 0; ks < 4; ks++) {
            #pragma unroll
            for (int ntp = 0; ntp < 4; ntp++) {
                int brow = ntp * 16 + (lane & 7) + (lane >> 4) * 8;
                int bcol = ks * 16 + ((lane >> 3) & 1) * 8;
                uint32_t off = (uint32_t)(brow * ASTR + bcol) * 2;
                uint32_t kbh[4];
                ldm_x4(kbh[0], kbh[1], kbh[2], kbh[3], sKh + boff + off);
                #pragma unroll
                for (int nt2 = 0; nt2 < 2; nt2++) {
                    mma_f16(Cs[ntp * 2 + nt2], qh[ks], &kbh[nt2 * 2]);
                }
            }
        }

        // scale + mask + online softmax
        float mn0 = m0, mn1 = m1;
        #pragma unroll
        for (int nt = 0; nt < 8; nt++) {
            int col = kt * 64 + nt * 8 + (lane & 3) * 2;
            float mka = msk[col], mkb = msk[col + 1];
            Cs[nt][0] = fmaf(Cs[nt][0], 0.125f, mka);
            Cs[nt][1] = fmaf(Cs[nt][1], 0.125f, mkb);
            Cs[nt][2] = fmaf(Cs[nt][2], 0.125f, mka);
            Cs[nt][3] = fmaf(Cs[nt][3], 0.125f, mkb);
            mn0 = fmaxf(mn0, fmaxf(Cs[nt][0], Cs[nt][1]));
            mn1 = fmaxf(mn1, fmaxf(Cs[nt][2], Cs[nt][3]));
        }
        mn0 = fmaxf(mn0, __shfl_xor_sync(0xffffffffu, mn0, 1));
        mn0 = fmaxf(mn0, __shfl_xor_sync(0xffffffffu, mn0, 2));
        mn1 = fmaxf(mn1, __shfl_xor_sync(0xffffffffu, mn1, 1));
        mn1 = fmaxf(mn1, __shfl_xor_sync(0xffffffffu, mn1, 2));

        float f0 = __expf(m0 - mn0), f1 = __expf(m1 - mn1);
        m0 = mn0; m1 = mn1;
        l0 *= f0; l1 *= f1;
        #pragma unroll
        for (int nt = 0; nt < 8; nt++) {
            Co[nt][0] *= f0; Co[nt][1] *= f0;
            Co[nt][2] *= f1; Co[nt][3] *= f1;
        }
        #pragma unroll
        for (int nt = 0; nt < 8; nt++) {
            Cs[nt][0] = __expf(Cs[nt][0] - m0);
            Cs[nt][1] = __expf(Cs[nt][1] - m0);
            Cs[nt][2] = __expf(Cs[nt][2] - m1);
            Cs[nt][3] = __expf(Cs[nt][3] - m1);
            l0 += Cs[nt][0] + Cs[nt][1];
            l1 += Cs[nt][2] + Cs[nt][3];
        }

        // O += P V
        #pragma unroll
        for (int kc = 0; kc < 4; kc++) {
            uint32_t phi[4];
            phi[0] = pack2_f16(Cs[2 * kc][0],     Cs[2 * kc][1]);
            phi[1] = pack2_f16(Cs[2 * kc][2],     Cs[2 * kc][3]);
            phi[2] = pack2_f16(Cs[2 * kc + 1][0], Cs[2 * kc + 1][1]);
            phi[3] = pack2_f16(Cs[2 * kc + 1][2], Cs[2 * kc + 1][3]);
            #pragma unroll
            for (int ntp = 0; ntp < 4; ntp++) {
                uint32_t off = (uint32_t)((kc * 16 + (lane & 15)) * ASTR +
                                          ntp * 16 + (lane >> 4) * 8) * 2;
                uint32_t vbh[4];
                ldm_x4_t(vbh[0], vbh[1], vbh[2], vbh[3], sVh + boff + off);
                #pragma unroll
                for (int nt2 = 0; nt2 < 2; nt2++) {
                    mma_f16(Co[ntp * 2 + nt2], phi, &vbh[nt2 * 2]);
                }
            }
        }
        __syncthreads();
    }

    l0 += __shfl_xor_sync(0xffffffffu, l0, 1);
    l0 += __shfl_xor_sync(0xffffffffu, l0, 2);
    l1 += __shfl_xor_sync(0xffffffffu, l1, 1);
    l1 += __shfl_xor_sync(0xffffffffu, l1, 2);
    float inv0 = 1.f / l0, inv1 = 1.f / l1;

    const int s0 = qt * 128 + wid * 16 + (lane >> 2);
    #pragma unroll
    for (int nt = 0; nt < 8; nt++) {
        int col = h * HD_ + nt * 8 + (lane & 3) * 2;
        size_t o0 = (size_t)(b * S_ + s0) * H_ + col;
        size_t o1 = (size_t)(b * S_ + s0 + 8) * H_ + col;
        *(uint32_t*)&g_Chi[o0] = pack2_f16(Co[nt][0] * inv0, Co[nt][1] * inv0);
        *(uint32_t*)&g_Chi[o1] = pack2_f16(Co[nt][2] * inv1, Co[nt][3] * inv1);
    }
}

// ---------------------------------------------------------------------------
// LayerNorm
// ---------------------------------------------------------------------------
__global__ __launch_bounds__(256) void ln_kernel(
    const float* __restrict__ gamma, const float* __restrict__ beta,
    float* __restrict__ out)
{
    const int row = blockIdx.x;
    const int tid = threadIdx.x;
    const float* x = g_x + (size_t)row * H_;

    float4 v = *(const float4*)&x[tid * 4];
    float s  = v.x + v.y + v.z + v.w;
    float ss = v.x * v.x + v.y * v.y + v.z * v.z + v.w * v.w;

    #pragma unroll
    for (int o = 16; o > 0; o >>= 1) {
        s  += __shfl_xor_sync(0xffffffffu, s,  o);
        ss += __shfl_xor_sync(0xffffffffu, ss, o);
    }
    __shared__ float rs[8], rss[8];
    int wid = tid >> 5, lid = tid & 31;
    if (lid == 0) { rs[wid] = s; rss[wid] = ss; }
    __syncthreads();
    if (wid == 0) {
        float a = (lid < 8) ? rs[lid]  : 0.f;
        float c = (lid < 8) ? rss[lid] : 0.f;
        #pragma unroll
        for (int o = 4; o > 0; o >>= 1) {
            a += __shfl_xor_sync(0xffffffffu, a, o);
            c += __shfl_xor_sync(0xffffffffu, c, o);
        }
        if (lid == 0) { rs[0] = a; rss[0] = c; }
    }
    __syncthreads();

    float mean = rs[0] * (1.f / H_);
    float var  = rss[0] * (1.f / H_) - mean * mean;
    float rstd = rsqrtf(var + LN_EPS);

    float4 g = *(const float4*)&gamma[tid * 4];
    float4 bt = *(const float4*)&beta[tid * 4];
    float4 y;
    y.x = (v.x - mean) * rstd * g.x + bt.x;
    y.y = (v.y - mean) * rstd * g.y + bt.y;
    y.z = (v.z - mean) * rstd * g.z + bt.z;
    y.w = (v.w - mean) * rstd * g.w + bt.w;
    *(float4*)&out[(size_t)row * H_ + tid * 4] = y;
}

// ---------------------------------------------------------------------------
extern "C" void kernel_launch(void* const* d_in, const int* in_sizes, int n_in,
                              void* d_out, int out_size)
{
    const float* hidden = (const float*)d_in[0];
    const float* mask   = (const float*)d_in[1];
    const float* Wq     = (const float*)d_in[2];
    const float* bq     = (const float*)d_in[3];
    const float* Wk     = (const float*)d_in[4];
    const float* bk     = (const float*)d_in[5];
    const float* Wv     = (const float*)d_in[6];
    const float* bv     = (const float*)d_in[7];
    const float* Wo     = (const float*)d_in[8];
    const float* bo     = (const float*)d_in[9];
    const float* gamma  = (const float*)d_in[10];
    const float* beta   = (const float*)d_in[11];
    float* out          = (float*)d_out;

    static int attr_set = 0;
    if (!attr_set) {
        cudaFuncSetAttribute(gemm_kernel, cudaFuncAttributeMaxDynamicSharedMemorySize, GEMM_SMEM);
        attr_set = 1;
    }

    unsigned short *xhi, *whi, *chi;
    cudaGetSymbolAddress((void**)&xhi, g_Xhi);
    cudaGetSymbolAddress((void**)&whi, g_Whi);
    cudaGetSymbolAddress((void**)&chi, g_Chi);

    split_all_kernel<<<(NSPLIT4 + 255) / 256, 256>>>(hidden, Wq, Wk, Wv, Wo, xhi, whi);

    dim3 qkv_grid(H_ / 64, M_ / 128, 3);
    gemm_kernel<<<qkv_grid, 256, GEMM_SMEM>>>(xhi, 0, bq, bk, bv, nullptr);

    dim3 attn_grid(S_ / 128, B_ * NH_);
    attn_kernel<<<attn_grid, 256>>>(mask);

    dim3 out_grid(H_ / 64, M_ / 128, 1);
    gemm_kernel<<<out_grid, 256, GEMM_SMEM>>>(chi, 3, bo, nullptr, nullptr, hidden);

    ln_kernel<<<M_, 256>>>(gamma, beta, out);
}